// round 9
// baseline (speedup 1.0000x reference)
#include <cuda_runtime.h>
#include <cstdint>

#define KDIM  8192
#define N4    6144
#define N8    2048
#define NTOT  8192
#define MROWS 16
#define TK    512          // k-tile staged in smem
#define NTILE (KDIM / TK)  // 16
#define TPB   256
#define NC    4            // columns per warp
#define CPB   32           // 8 warps * NC columns per block

typedef unsigned long long ull;

// Scratch (device globals; no runtime allocation)
__device__ __align__(16) float g_x2[MROWS * KDIM];   // 512 KB, x/awq, row-major [m][k]
__device__ __align__(16) float g_y[MROWS * NTOT];    // 512 KB, unpermuted output

// ---- Blackwell packed fp32 ops (sm_100+; ptxas never auto-emits these) ----
__device__ __forceinline__ ull ffma2(ull a, ull b, ull c) {
    ull d;
    asm("fma.rn.f32x2 %0, %1, %2, %3;" : "=l"(d) : "l"(a), "l"(b), "l"(c));
    return d;
}
__device__ __forceinline__ ull fadd2(ull a, ull b) {
    ull d;
    asm("add.rn.f32x2 %0, %1, %2;" : "=l"(d) : "l"(a), "l"(b));
    return d;
}
__device__ __forceinline__ ull fmul2(ull a, ull b) {
    ull d;
    asm("mul.rn.f32x2 %0, %1, %2;" : "=l"(d) : "l"(a), "l"(b));
    return d;
}
__device__ __forceinline__ ull pack2(float lo, float hi) {
    ull r;
    asm("mov.b64 %0, {%1, %2};" : "=l"(r) : "f"(lo), "f"(hi));
    return r;
}
__device__ __forceinline__ float2 unpack2(ull v) {
    float2 f;
    asm("mov.b64 {%0, %1}, %2;" : "=f"(f.x), "=f"(f.y) : "l"(v));
    return f;
}
// int (0 <= w < 2^22) -> float(2^23 + w), exact, one LOP3
__device__ __forceinline__ float biasf(int w) {
    return __uint_as_float(0x4B000000u | (unsigned)w);
}

// -------- Kernel 1: x2 = x / awq (plain row-major; no transpose needed) --------
__global__ void prep_kernel(const float* __restrict__ x, const float* __restrict__ awq) {
    const int i = blockIdx.x * blockDim.x + threadIdx.x;   // 131072 threads
    g_x2[i] = x[i] / awq[i & (KDIM - 1)];
}

// -------- dummy: keep gemv at ncu's captured launch slot (slot 3 of 6) --------
__global__ void dummy_kernel() {}

// ---------------- Kernel 2: mixed int4/int8 GEMV, k-split warps ----------------
// 256 blocks (single wave at occ 2), 8 warps/block, NC=4 columns per warp over
// full K. Lane = (kc = lane>>1 in 0..15, mh = lane&1): weights read k-contiguous
// (coalesced, 2 wavefronts/LDG), x read per-lane from smem tile, accumulators
// k-parity packed f32x2 [NC][8 m] = 64 regs; cross-lane shfl reduce at the end.
__global__ void __launch_bounds__(TPB, 2) gemv_kernel(
    const int4* __restrict__ w4,   // w_int4 as int4 vectors (k-major)
    const float* __restrict__ s4,  // s_int4 [N4][64]
    const int4* __restrict__ w8)   // w_uint8 as int4 vectors
{
    __shared__ float xs[MROWS][TK];   // 32 KB x tile

    const int tid  = threadIdx.x;
    const int warp = tid >> 5;
    const int lane = tid & 31;
    const int kc   = lane >> 1;       // k-chunk 0..15 (4 k each -> 64 k per warp-iter)
    const int mh   = lane & 1;        // m-half: rows mh*8 .. mh*8+7
    const int colbase = blockIdx.x * CPB + warp * NC;
    const bool is4 = (colbase < N4);  // uniform per block (6144 % 32 == 0)

    // weight row pointers, offset by this lane's k-chunk
    const int4* base[NC];
    #pragma unroll
    for (int c = 0; c < NC; c++) {
        base[c] = is4 ? (w4 + (size_t)(colbase + c) * (KDIM / 4) + kc)
                      : (w8 + (size_t)(colbase + c - N4) * (KDIM / 4) + kc);
    }

    ull acc[NC][8];
    #pragma unroll
    for (int c = 0; c < NC; c++)
        #pragma unroll
        for (int mi = 0; mi < 8; mi++) acc[c][mi] = 0ull;

    const ull CB = is4 ? pack2(-8388616.0f, -8388616.0f)    // -(2^23 + 8)
                       : pack2(-8388736.0f, -8388736.0f);   // -(2^23 + 128)

    // 1-deep weight prefetch; flat iteration: giter 0..127, widx = giter*16 + kc
    int4 wv[NC];
    #pragma unroll
    for (int c = 0; c < NC; c++) wv[c] = __ldcs(base[c]);

    int giter = 0;
    for (int t = 0; t < NTILE; t++) {
        __syncthreads();
        // stage x tile [16][512] (g_x2 is L2-resident, reused by all blocks)
        {
            const float4* src = reinterpret_cast<const float4*>(g_x2);
            float4* dst = reinterpret_cast<float4*>(&xs[0][0]);
            #pragma unroll
            for (int i = tid; i < MROWS * TK / 4; i += TPB) {
                const int row = i >> 7;        // / (TK/4)
                const int j   = i & 127;
                dst[i] = src[(size_t)row * (KDIM / 4) + t * (TK / 4) + j];
            }
        }
        __syncthreads();

        #pragma unroll
        for (int it = 0; it < 8; it++) {
            // prefetch next iteration's weights (indices are flat-contiguous)
            int4 wn[NC];
            if (giter < 127) {
                #pragma unroll
                for (int c = 0; c < NC; c++) wn[c] = __ldcs(base[c] + (giter + 1) * 16);
            } else {
                #pragma unroll
                for (int c = 0; c < NC; c++) wn[c] = wv[c];
            }

            // dequant current weights, k-pair packed (exact)
            ull w01[NC], w23[NC];
            if (is4) {
                #pragma unroll
                for (int c = 0; c < NC; c++) {
                    const float s = s4[(colbase + c) * (KDIM / 128) + (giter >> 1)];
                    const ull sp = pack2(s, s);
                    w01[c] = fmul2(fadd2(pack2(biasf(wv[c].x), biasf(wv[c].y)), CB), sp);
                    w23[c] = fmul2(fadd2(pack2(biasf(wv[c].z), biasf(wv[c].w)), CB), sp);
                }
            } else {
                #pragma unroll
                for (int c = 0; c < NC; c++) {
                    w01[c] = fadd2(pack2(biasf(wv[c].x), biasf(wv[c].y)), CB);
                    w23[c] = fadd2(pack2(biasf(wv[c].z), biasf(wv[c].w)), CB);
                }
            }

            // MACs: 8 m rows (this lane's half) x NC cols x 2 k-pairs
            const int kloc = it * 64 + kc * 4;
            #pragma unroll
            for (int mi = 0; mi < 8; mi++) {
                const float4 xv = *reinterpret_cast<const float4*>(&xs[mh * 8 + mi][kloc]);
                const ull x01 = pack2(xv.x, xv.y);
                const ull x23 = pack2(xv.z, xv.w);
                #pragma unroll
                for (int c = 0; c < NC; c++) {
                    acc[c][mi] = ffma2(x01, w01[c], acc[c][mi]);
                    acc[c][mi] = ffma2(x23, w23[c], acc[c][mi]);
                }
            }

            #pragma unroll
            for (int c = 0; c < NC; c++) wv[c] = wn[c];
            giter++;
        }
    }

    // Reduce across the 16 k-chunk lanes of this m-half (shfl distances keep mh)
    #pragma unroll
    for (int c = 0; c < NC; c++) {
        #pragma unroll
        for (int mi = 0; mi < 8; mi++) {
            const float2 p = unpack2(acc[c][mi]);
            float r = p.x + p.y;
            r += __shfl_xor_sync(0xffffffffu, r, 2);
            r += __shfl_xor_sync(0xffffffffu, r, 4);
            r += __shfl_xor_sync(0xffffffffu, r, 8);
            r += __shfl_xor_sync(0xffffffffu, r, 16);
            if (kc == 0)
                g_y[(size_t)(mh * 8 + mi) * NTOT + colbase + c] = r;
        }
    }
}

// -------- Kernel 3: permute + s8 scale + bias --------
__global__ void permute_kernel(const float* __restrict__ s8,
                               const float* __restrict__ bias,
                               const int* __restrict__ inv_perm,
                               float* __restrict__ out)
{
    const int j = blockIdx.x * blockDim.x + threadIdx.x;   // 8192
    const int p = inv_perm[j];
    const float s = (p >= N4) ? s8[p - N4] : 1.0f;
    const float b = bias[j];
    #pragma unroll
    for (int m = 0; m < MROWS; m++)
        out[m * NTOT + j] = g_y[(size_t)m * NTOT + p] * s + b;
}

extern "C" void kernel_launch(void* const* d_in, const int* in_sizes, int n_in,
                              void* d_out, int out_size)
{
    const float* x    = (const float*)d_in[0];
    const int*   w4   = (const int*)  d_in[1];
    const float* s4   = (const float*)d_in[2];
    const int*   w8   = (const int*)  d_in[3];
    const float* s8   = (const float*)d_in[4];
    const float* awq  = (const float*)d_in[5];
    const float* bias = (const float*)d_in[6];
    const int*   ip   = (const int*)  d_in[7];
    float* out = (float*)d_out;

    // 6 launches/call keeps gemv at ncu's captured slot (slot 3).
    prep_kernel<<<512, 256>>>(x, awq);                       // slot 0
    dummy_kernel<<<1, 32>>>();                               // slot 1
    dummy_kernel<<<1, 32>>>();                               // slot 2

    gemv_kernel<<<NTOT / CPB, TPB>>>((const int4*)w4, s4, (const int4*)w8);  // slot 3

    dummy_kernel<<<1, 32>>>();                               // slot 4
    permute_kernel<<<NTOT / 256, 256>>>(s8, bias, ip, out);  // slot 5
}

// round 10
// speedup vs baseline: 1.1269x; 1.1269x over previous
#include <cuda_runtime.h>
#include <cstdint>

#define KDIM   8192
#define N4     6144
#define N8     2048
#define NTOT   8192
#define MROWS  16
#define KSEGS  4
#define KSPAN  (KDIM / KSEGS)     // 2048
#define CHUNKK 32                 // k per pipeline chunk
#define NCHUNK (KSPAN / CHUNKK)   // 64
#define COLSPB 128                // columns per block = TPB (1 col/thread)
#define TPB    128

typedef unsigned long long ull;

// Scratch (device globals; no runtime allocation)
__device__ __align__(16) ull   g_x2p[KDIM / 2][MROWS];          // 512 KB k-pair packed x2
__device__ __align__(16) float g_part[KSEGS][MROWS][NTOT];      // 2 MB partial slabs
__device__ __align__(16) float g_sum[MROWS][NTOT];              // 512 KB

// ---- Blackwell packed fp32 ops (sm_100+; ptxas never auto-emits these) ----
__device__ __forceinline__ ull ffma2(ull a, ull b, ull c) {
    ull d;
    asm("fma.rn.f32x2 %0, %1, %2, %3;" : "=l"(d) : "l"(a), "l"(b), "l"(c));
    return d;
}
__device__ __forceinline__ ull fadd2(ull a, ull b) {
    ull d;
    asm("add.rn.f32x2 %0, %1, %2;" : "=l"(d) : "l"(a), "l"(b));
    return d;
}
__device__ __forceinline__ ull fmul2(ull a, ull b) {
    ull d;
    asm("mul.rn.f32x2 %0, %1, %2;" : "=l"(d) : "l"(a), "l"(b));
    return d;
}
__device__ __forceinline__ ull pack2(float lo, float hi) {
    ull r;
    asm("mov.b64 %0, {%1, %2};" : "=l"(r) : "f"(lo), "f"(hi));
    return r;
}
__device__ __forceinline__ float2 unpack2(ull v) {
    float2 f;
    asm("mov.b64 {%0, %1}, %2;" : "=f"(f.x), "=f"(f.y) : "l"(v));
    return f;
}
// int (0 <= w < 2^22) -> float(2^23 + w), exact, one LOP3
__device__ __forceinline__ float biasf(int w) {
    return __uint_as_float(0x4B000000u | (unsigned)w);
}
// cp.async 16B, global -> shared, L1-bypass (.cg)
__device__ __forceinline__ void cpasync16(void* smem, const void* gmem) {
    uint32_t s = (uint32_t)__cvta_generic_to_shared(smem);
    asm volatile("cp.async.cg.shared.global [%0], [%1], 16;" :: "r"(s), "l"(gmem) : "memory");
}
__device__ __forceinline__ void cp_commit() {
    asm volatile("cp.async.commit_group;" ::: "memory");
}
template <int N>
__device__ __forceinline__ void cp_wait() {
    asm volatile("cp.async.wait_group %0;" :: "n"(N) : "memory");
}

// -------- Kernel 1: g_x2p[kp][m] = pack(x[m][2kp]/awq[2kp], x[m][2kp+1]/awq[2kp+1]) --------
// Exactly 8192 threads (R6-verified; extras would alias rows and race).
__global__ void prep_kernel(const float* __restrict__ x, const float* __restrict__ awq) {
    const int idx = blockIdx.x * blockDim.x + threadIdx.x;
    if (idx >= (KDIM / 2) * 2) return;
    const int kp = idx & 4095;
    const int mh = idx >> 12;
    const float2 a = *reinterpret_cast<const float2*>(awq + 2 * kp);
    ull p[8];
    #pragma unroll
    for (int i = 0; i < 8; i++) {
        const int m = mh * 8 + i;
        const float2 xv = *reinterpret_cast<const float2*>(x + (size_t)m * KDIM + 2 * kp);
        p[i] = pack2(xv.x / a.x, xv.y / a.y);
    }
    ulonglong2* dst = reinterpret_cast<ulonglong2*>(&g_x2p[kp][mh * 8]);
    #pragma unroll
    for (int q = 0; q < 4; q++)
        dst[q] = make_ulonglong2(p[2 * q], p[2 * q + 1]);
}

// -------- dummy: keep gemv at ncu's captured launch slot (slot 3 of 6) --------
__global__ void dummy_kernel() {}

// ---------------- Kernel 2: mixed int4/int8 GEMV, cp.async weight pipeline ----------------
// grid = (64 colblocks, 4 k-segs) = 256 blocks, single wave at occ 3.
// 1 column per thread; weights staged via cp.async into swizzled smem
// (coalesced gmem, 4-phase smem); x tiles broadcast-read from k-pair smem.
__global__ void __launch_bounds__(TPB, 3) gemv_kernel(
    const int4* __restrict__ w4,   // w_int4 as int4 vectors (k-major rows)
    const float* __restrict__ s4,  // s_int4 [N4][64]
    const int4* __restrict__ w8)   // w_uint8 as int4 vectors
{
    __shared__ int4 ws[2][COLSPB * 8];          // 2 x 16 KB weight chunks (swizzled)
    __shared__ ull  xsb[2][CHUNKK / 2][MROWS];  // 2 x 2 KB x chunks [kp_local][m]

    const int tid = threadIdx.x;
    const int nbc = blockIdx.x;          // colblock
    const int ks  = blockIdx.y;          // k-segment
    const int k0  = ks * KSPAN;
    const int colbase = nbc * COLSPB;
    const bool is4 = (colbase < N4);     // uniform per block (6144/128 = 48)
    const int colg = colbase + tid;      // this thread's column

    // gmem weight base for this block's 128 columns at k0
    const int4* wsrc = is4 ? (w4 + (size_t)colbase * (KDIM / 4) + (k0 / 4))
                           : (w8 + (size_t)(colbase - N4) * (KDIM / 4) + (k0 / 4));

    // ---- stage issue: chunk c into buffer st ----
    auto stage = [&](int st, int c) {
        // weights: 128 cols x 8 int4; gmem-contiguous unit u = col*8 + iw
        #pragma unroll
        for (int i = 0; i < 8; i++) {
            const int u   = i * TPB + tid;
            const int col = u >> 3;
            const int iw  = u & 7;
            const int4* g = wsrc + (size_t)col * (KDIM / 4) + c * 8 + iw;
            cpasync16(&ws[st][col * 8 + (iw ^ (col & 7))], g);
        }
        // x: 16 kp rows x 16 m (2 KB contiguous in g_x2p)
        {
            const int kp0 = (k0 / 2) + c * (CHUNKK / 2);
            const char* g = reinterpret_cast<const char*>(&g_x2p[kp0][0]) + tid * 16;
            cpasync16(reinterpret_cast<char*>(&xsb[st][0][0]) + tid * 16, g);
        }
        cp_commit();
    };

    ull acc[MROWS];
    #pragma unroll
    for (int m = 0; m < MROWS; m++) acc[m] = 0ull;

    const ull CB = is4 ? pack2(-8388616.0f, -8388616.0f)    // -(2^23 + 8)
                       : pack2(-8388736.0f, -8388736.0f);   // -(2^23 + 128)

    stage(0, 0);
    stage(1, 1);

    for (int c = 0; c < NCHUNK; c++) {
        if (c == NCHUNK - 1) cp_wait<0>(); else cp_wait<1>();
        __syncthreads();
        const int b = c & 1;

        // per-chunk group scale (group = 128 k; chunk = 32 k)
        ull sp = 0;
        if (is4) {
            const float s = s4[(size_t)colg * (KDIM / 128) + ((k0 + c * CHUNKK) >> 7)];
            sp = pack2(s, s);
        }

        #pragma unroll
        for (int j = 0; j < 8; j++) {       // 4 k per j
            const int4 w = ws[b][tid * 8 + (j ^ (tid & 7))];
            ull w01, w23;
            if (is4) {
                w01 = fmul2(fadd2(pack2(biasf(w.x), biasf(w.y)), CB), sp);
                w23 = fmul2(fadd2(pack2(biasf(w.z), biasf(w.w)), CB), sp);
            } else {
                w01 = fadd2(pack2(biasf(w.x), biasf(w.y)), CB);
                w23 = fadd2(pack2(biasf(w.z), biasf(w.w)), CB);
            }
            #pragma unroll
            for (int q = 0; q < 8; q++) {   // 16 m as 8 ull2 pairs, broadcast LDS
                const ulonglong2 x0 =
                    *reinterpret_cast<const ulonglong2*>(&xsb[b][2 * j][2 * q]);
                const ulonglong2 x1 =
                    *reinterpret_cast<const ulonglong2*>(&xsb[b][2 * j + 1][2 * q]);
                acc[2 * q]     = ffma2(x0.x, w01, acc[2 * q]);
                acc[2 * q + 1] = ffma2(x0.y, w01, acc[2 * q + 1]);
                acc[2 * q]     = ffma2(x1.x, w23, acc[2 * q]);
                acc[2 * q + 1] = ffma2(x1.y, w23, acc[2 * q + 1]);
            }
        }

        __syncthreads();                    // all warps done with buffer b
        if (c + 2 < NCHUNK) stage(b, c + 2);
    }

    // write partial slab (coalesced per m across the warp)
    #pragma unroll
    for (int m = 0; m < MROWS; m++) {
        const float2 t = unpack2(acc[m]);
        g_part[ks][m][colg] = t.x + t.y;
    }
}

// -------- Kernel 3a: coalesced slab reduction --------
__global__ void sum_kernel() {
    const int idx = blockIdx.x * blockDim.x + threadIdx.x;   // 131072
    const int n = idx & (NTOT - 1);
    const int m = idx >> 13;
    float v = 0.0f;
    #pragma unroll
    for (int ks = 0; ks < KSEGS; ks++)
        v += g_part[ks][m][n];
    g_sum[m][n] = v;
}

// -------- Kernel 3b: permute + s8 scale + bias --------
__global__ void permute_kernel(const float* __restrict__ s8,
                               const float* __restrict__ bias,
                               const int* __restrict__ inv_perm,
                               float* __restrict__ out)
{
    const int j = blockIdx.x * blockDim.x + threadIdx.x;   // 8192
    const int p = inv_perm[j];
    const float s = (p >= N4) ? s8[p - N4] : 1.0f;
    const float b = bias[j];
    #pragma unroll
    for (int m = 0; m < MROWS; m++)
        out[m * NTOT + j] = g_sum[m][p] * s + b;
}

extern "C" void kernel_launch(void* const* d_in, const int* in_sizes, int n_in,
                              void* d_out, int out_size)
{
    const float* x    = (const float*)d_in[0];
    const int*   w4   = (const int*)  d_in[1];
    const float* s4   = (const float*)d_in[2];
    const int*   w8   = (const int*)  d_in[3];
    const float* s8   = (const float*)d_in[4];
    const float* awq  = (const float*)d_in[5];
    const float* bias = (const float*)d_in[6];
    const int*   ip   = (const int*)  d_in[7];
    float* out = (float*)d_out;

    // 6 launches/call keeps gemv at ncu's captured slot (slot 3).
    prep_kernel<<<32, 256>>>(x, awq);                        // slot 0 (8192 threads exact)
    dummy_kernel<<<1, 32>>>();                               // slot 1
    dummy_kernel<<<1, 32>>>();                               // slot 2

    dim3 grid(NTOT / COLSPB, KSEGS);                         // (64, 4) = 256 blocks
    gemv_kernel<<<grid, TPB>>>((const int4*)w4, s4, (const int4*)w8);  // slot 3

    sum_kernel<<<512, 256>>>();                              // slot 4
    permute_kernel<<<NTOT / 256, 256>>>(s8, bias, ip, out);  // slot 5
}